// round 4
// baseline (speedup 1.0000x reference)
#include <cuda_runtime.h>

#define IN_DIM  1024
#define OUT_DIM 512
#define B_DIM   128
#define OT      16      // output tile per block
#define BT      16      // batch tile per block
#define SPLITS  8
#define I_PER   (IN_DIM / SPLITS)   // 128 inputs per split
#define LDW     (I_PER + 4)         // 132: 16B-aligned, conflict-free rows

// Precomputed W_eff (tanh.approx consumes z directly).
__device__ float g_w[OUT_DIM * IN_DIM];
// Partial sums: [split][b][o]
__device__ float g_part[SPLITS * B_DIM * OUT_DIM];

__device__ __forceinline__ float tanh_approx(float x) {
    float y;
    asm("tanh.approx.f32 %0, %1;" : "=f"(y) : "f"(x));
    return y;
}
__device__ __forceinline__ float rcp_approx(float x) {
    float y;
    asm("rcp.approx.f32 %0, %1;" : "=f"(y) : "f"(x));
    return y;
}

// Kernel 1: W_eff[o,i] = softmax(theta[o,i,:]) . {0, W, tanh(W), sin(W)}
// 2 elements per thread; called per half (elem_base selects the half).
__global__ __launch_bounds__(256)
void weff_kernel(const float* __restrict__ W,
                 const float* __restrict__ theta,
                 int elem_base) {
    int e = elem_base + (blockIdx.x * blockDim.x + threadIdx.x) * 2;
    float4 t0 = reinterpret_cast<const float4*>(theta)[e];
    float4 t1 = reinterpret_cast<const float4*>(theta)[e + 1];
    float2 wv = *reinterpret_cast<const float2*>(W + e);

    float2 r;
    {
        float a = __expf(t0.x), b = __expf(t0.y), c = __expf(t0.z), d = __expf(t0.w);
        float inv = rcp_approx(a + b + c + d);
        r.x = (b * wv.x + c * tanh_approx(wv.x) + d * __sinf(wv.x)) * inv;
    }
    {
        float a = __expf(t1.x), b = __expf(t1.y), c = __expf(t1.z), d = __expf(t1.w);
        float inv = rcp_approx(a + b + c + d);
        r.y = (b * wv.y + c * tanh_approx(wv.y) + d * __sinf(wv.y)) * inv;
    }
    *reinterpret_cast<float2*>(g_w + e) = r;
}

// Kernel 2: partial[s][b][o] = sum_{i in split s} tanh(x[b,i] * W_eff[o,i])
// One 128-wide split staged in smem per block; z_base selects the half.
__global__ __launch_bounds__(OT * BT)
void fbn_main_kernel(const float* __restrict__ x, int z_base) {
    __shared__ float xs[BT][LDW];
    __shared__ float ws[OT][LDW];

    const int tx = threadIdx.x;            // o within tile
    const int ty = threadIdx.y;            // b within tile
    const int o0 = blockIdx.x * OT;
    const int b0 = blockIdx.y * BT;
    const int split = z_base + blockIdx.z;
    const int c0 = split * I_PER;
    const int tid = ty * OT + tx;

    const int r = tid >> 4;                // staging row 0..15
    const int q = tid & 15;                // staging float4 lane 0..15

    // Stage 16x128 x-tile and 16x128 w-tile: 4 LDG.128 per thread.
    const float4* xg = reinterpret_cast<const float4*>(x   + (b0 + r) * IN_DIM + c0);
    const float4* wg = reinterpret_cast<const float4*>(g_w + (o0 + r) * IN_DIM + c0);
    float4 xv0 = xg[q];      float4 wv0 = wg[q];
    float4 xv1 = xg[q + 16]; float4 wv1 = wg[q + 16];
    *reinterpret_cast<float4*>(&xs[r][(q     ) * 4]) = xv0;
    *reinterpret_cast<float4*>(&ws[r][(q     ) * 4]) = wv0;
    *reinterpret_cast<float4*>(&xs[r][(q + 16) * 4]) = xv1;
    *reinterpret_cast<float4*>(&ws[r][(q + 16) * 4]) = wv1;
    __syncthreads();

    float acc0 = 0.0f, acc1 = 0.0f;
    #pragma unroll
    for (int i = 0; i < I_PER; i += 8) {
        float4 xa = *reinterpret_cast<const float4*>(&xs[ty][i]);
        float4 wa = *reinterpret_cast<const float4*>(&ws[tx][i]);
        float4 xb = *reinterpret_cast<const float4*>(&xs[ty][i + 4]);
        float4 wb = *reinterpret_cast<const float4*>(&ws[tx][i + 4]);
        acc0 += tanh_approx(xa.x * wa.x);
        acc1 += tanh_approx(xa.y * wa.y);
        acc0 += tanh_approx(xa.z * wa.z);
        acc1 += tanh_approx(xa.w * wa.w);
        acc0 += tanh_approx(xb.x * wb.x);
        acc1 += tanh_approx(xb.y * wb.y);
        acc0 += tanh_approx(xb.z * wb.z);
        acc1 += tanh_approx(xb.w * wb.w);
    }

    g_part[(split * B_DIM + b0 + ty) * OUT_DIM + o0 + tx] = acc0 + acc1;
}

// Kernel 3: out[b][o] = bias[o] + sum_s partial[s][b][o]
__global__ void reduce_kernel(const float* __restrict__ bias,
                              float* __restrict__ out) {
    int idx = blockIdx.x * blockDim.x + threadIdx.x;   // 0..65535
    float s = bias[idx & (OUT_DIM - 1)];
    #pragma unroll
    for (int p = 0; p < SPLITS; p++)
        s += g_part[p * B_DIM * OUT_DIM + idx];
    out[idx] = s;
}

extern "C" void kernel_launch(void* const* d_in, const int* in_sizes, int n_in,
                              void* d_out, int out_size) {
    const float* x     = (const float*)d_in[0];   // (128, 1024)
    const float* W     = (const float*)d_in[1];   // (512, 1024)
    const float* bias  = (const float*)d_in[2];   // (512,)
    const float* theta = (const float*)d_in[3];   // (512, 1024, 4)
    float* out = (float*)d_out;                   // (128, 512)

    (void)in_sizes; (void)n_in; (void)out_size;

    // Created once on the first (non-captured, correctness) call; reused by
    // the capture call so the graph gets a stable multi-stream topology.
    static cudaStream_t s2 = []() {
        cudaStream_t s; cudaStreamCreateWithFlags(&s, cudaStreamNonBlocking); return s;
    }();
    static cudaEvent_t evA = []() {
        cudaEvent_t e; cudaEventCreateWithFlags(&e, cudaEventDisableTiming); return e;
    }();
    static cudaEvent_t evB = []() {
        cudaEvent_t e; cudaEventCreateWithFlags(&e, cudaEventDisableTiming); return e;
    }();
    static cudaEvent_t evF = []() {
        cudaEvent_t e; cudaEventCreateWithFlags(&e, cudaEventDisableTiming); return e;
    }();

    const int HALF_ELEMS = OUT_DIM * IN_DIM / 2;          // 262144
    const int WEFF_BLOCKS = HALF_ELEMS / (2 * 256);       // 512 blocks per half

    // Stream 0 (capture stream): weff halves.
    weff_kernel<<<WEFF_BLOCKS, 256>>>(W, theta, 0);
    cudaEventRecord(evA, 0);
    weff_kernel<<<WEFF_BLOCKS, 256>>>(W, theta, HALF_ELEMS);
    cudaEventRecord(evB, 0);

    // Stream s2: main halves, each gated on its weff half; overlaps weff half 1.
    dim3 grid(OUT_DIM / OT, B_DIM / BT, SPLITS / 2);   // (32, 8, 4) = 1024 blocks
    dim3 block(OT, BT);                                // 256 threads
    cudaStreamWaitEvent(s2, evA, 0);
    fbn_main_kernel<<<grid, block, 0, s2>>>(x, 0);
    cudaStreamWaitEvent(s2, evB, 0);
    fbn_main_kernel<<<grid, block, 0, s2>>>(x, SPLITS / 2);

    reduce_kernel<<<(B_DIM * OUT_DIM) / 256, 256, 0, s2>>>(bias, out);

    // Join back to the capture stream.
    cudaEventRecord(evF, s2);
    cudaStreamWaitEvent(0, evF, 0);
}

// round 5
// speedup vs baseline: 1.0521x; 1.0521x over previous
#include <cuda_runtime.h>

#define IN_DIM  1024
#define OUT_DIM 512
#define B_DIM   128
#define OT      16      // output tile per block
#define BT      16      // batch tile per block
#define SPLITS  4
#define I_PER   (IN_DIM / SPLITS)   // 256 inputs per split
#define LDW     (I_PER + 4)         // 260: 16B-aligned, conflict-free rows

// Precomputed W_eff (tanh.approx consumes z directly).
__device__ float g_w[OUT_DIM * IN_DIM];
// Partial sums: [split][b][o]
__device__ float g_part[SPLITS * B_DIM * OUT_DIM];

__device__ __forceinline__ float tanh_approx(float x) {
    float y;
    asm("tanh.approx.f32 %0, %1;" : "=f"(y) : "f"(x));
    return y;
}
__device__ __forceinline__ float rcp_approx(float x) {
    float y;
    asm("rcp.approx.f32 %0, %1;" : "=f"(y) : "f"(x));
    return y;
}

__device__ __forceinline__ float weff_one(float4 t, float w) {
    float a = __expf(t.x), b = __expf(t.y), c = __expf(t.z), d = __expf(t.w);
    float inv = rcp_approx(a + b + c + d);
    return (b * w + c * tanh_approx(w) + d * __sinf(w)) * inv;
}

// Kernel 1: W_eff[o,i] = softmax(theta[o,i,:]) . {0, W, tanh(W), sin(W)}
// 8 elements per thread, 10 front-batched LDG.128 (MLP=10) to hide DRAM latency.
// 128-thread blocks, no reg cap -> ptxas keeps all loads in flight.
__global__ __launch_bounds__(128)
void weff_kernel(const float* __restrict__ W,
                 const float* __restrict__ theta) {
    int e = (blockIdx.x * 128 + threadIdx.x) * 8;   // first element of 8

    const float4* t4 = reinterpret_cast<const float4*>(theta);
    const float4* w4 = reinterpret_cast<const float4*>(W);

    // Front-batched loads: 8x theta float4 + 2x W float4.
    float4 t0 = t4[e + 0];
    float4 t1 = t4[e + 1];
    float4 t2 = t4[e + 2];
    float4 t3 = t4[e + 3];
    float4 t4v = t4[e + 4];
    float4 t5 = t4[e + 5];
    float4 t6 = t4[e + 6];
    float4 t7 = t4[e + 7];
    float4 wa = w4[e / 4];
    float4 wb = w4[e / 4 + 1];

    float4 r0, r1;
    r0.x = weff_one(t0,  wa.x);
    r0.y = weff_one(t1,  wa.y);
    r0.z = weff_one(t2,  wa.z);
    r0.w = weff_one(t3,  wa.w);
    r1.x = weff_one(t4v, wb.x);
    r1.y = weff_one(t5,  wb.y);
    r1.z = weff_one(t6,  wb.z);
    r1.w = weff_one(t7,  wb.w);

    reinterpret_cast<float4*>(g_w)[e / 4]     = r0;
    reinterpret_cast<float4*>(g_w)[e / 4 + 1] = r1;
}

// Kernel 2: partial[s][b][o] = sum_{i in split s} tanh(x[b,i] * W_eff[o,i])
// Full 256-wide split staged in smem once per block (R3 config: at MUFU floor).
__global__ __launch_bounds__(OT * BT)
void fbn_main_kernel(const float* __restrict__ x) {
    __shared__ float xs[BT][LDW];
    __shared__ float ws[OT][LDW];

    const int tx = threadIdx.x;            // o within tile
    const int ty = threadIdx.y;            // b within tile
    const int o0 = blockIdx.x * OT;
    const int b0 = blockIdx.y * BT;
    const int c0 = blockIdx.z * I_PER;
    const int tid = ty * OT + tx;

    const int r = tid >> 4;                // staging row 0..15
    const int q = tid & 15;                // staging float4 lane 0..15

    // Stage 16x256 x-tile and 16x256 w-tile: 8 LDG.128 per thread, batched.
    const float4* xg = reinterpret_cast<const float4*>(x   + (b0 + r) * IN_DIM + c0);
    const float4* wg = reinterpret_cast<const float4*>(g_w + (o0 + r) * IN_DIM + c0);
    float4 xv0 = xg[q];      float4 wv0 = wg[q];
    float4 xv1 = xg[q + 16]; float4 wv1 = wg[q + 16];
    float4 xv2 = xg[q + 32]; float4 wv2 = wg[q + 32];
    float4 xv3 = xg[q + 48]; float4 wv3 = wg[q + 48];
    *reinterpret_cast<float4*>(&xs[r][(q     ) * 4]) = xv0;
    *reinterpret_cast<float4*>(&ws[r][(q     ) * 4]) = wv0;
    *reinterpret_cast<float4*>(&xs[r][(q + 16) * 4]) = xv1;
    *reinterpret_cast<float4*>(&ws[r][(q + 16) * 4]) = wv1;
    *reinterpret_cast<float4*>(&xs[r][(q + 32) * 4]) = xv2;
    *reinterpret_cast<float4*>(&ws[r][(q + 32) * 4]) = wv2;
    *reinterpret_cast<float4*>(&xs[r][(q + 48) * 4]) = xv3;
    *reinterpret_cast<float4*>(&ws[r][(q + 48) * 4]) = wv3;
    __syncthreads();

    float acc0 = 0.0f, acc1 = 0.0f;
    #pragma unroll
    for (int i = 0; i < I_PER; i += 8) {
        float4 xa = *reinterpret_cast<const float4*>(&xs[ty][i]);
        float4 wa = *reinterpret_cast<const float4*>(&ws[tx][i]);
        float4 xb = *reinterpret_cast<const float4*>(&xs[ty][i + 4]);
        float4 wb = *reinterpret_cast<const float4*>(&ws[tx][i + 4]);
        acc0 += tanh_approx(xa.x * wa.x);
        acc1 += tanh_approx(xa.y * wa.y);
        acc0 += tanh_approx(xa.z * wa.z);
        acc1 += tanh_approx(xa.w * wa.w);
        acc0 += tanh_approx(xb.x * wb.x);
        acc1 += tanh_approx(xb.y * wb.y);
        acc0 += tanh_approx(xb.z * wb.z);
        acc1 += tanh_approx(xb.w * wb.w);
    }

    g_part[(blockIdx.z * B_DIM + b0 + ty) * OUT_DIM + o0 + tx] = acc0 + acc1;
}

// Kernel 3: out[b][o] = bias[o] + sum_s partial[s][b][o]
__global__ void reduce_kernel(const float* __restrict__ bias,
                              float* __restrict__ out) {
    int idx = blockIdx.x * blockDim.x + threadIdx.x;   // 0..65535
    float s = bias[idx & (OUT_DIM - 1)];
    #pragma unroll
    for (int p = 0; p < SPLITS; p++)
        s += g_part[p * B_DIM * OUT_DIM + idx];
    out[idx] = s;
}

extern "C" void kernel_launch(void* const* d_in, const int* in_sizes, int n_in,
                              void* d_out, int out_size) {
    const float* x     = (const float*)d_in[0];   // (128, 1024)
    const float* W     = (const float*)d_in[1];   // (512, 1024)
    const float* bias  = (const float*)d_in[2];   // (512,)
    const float* theta = (const float*)d_in[3];   // (512, 1024, 4)
    float* out = (float*)d_out;                   // (128, 512)

    (void)in_sizes; (void)n_in; (void)out_size;

    // 512K elements / 8 per thread / 128 per block = 512 blocks
    weff_kernel<<<(OUT_DIM * IN_DIM) / (8 * 128), 128>>>(W, theta);

    dim3 grid(OUT_DIM / OT, B_DIM / BT, SPLITS);   // (32, 8, 4) = 1024 blocks
    dim3 block(OT, BT);                            // 256 threads
    fbn_main_kernel<<<grid, block>>>(x);

    reduce_kernel<<<(B_DIM * OUT_DIM) / 256, 256>>>(bias, out);
}

// round 6
// speedup vs baseline: 1.1266x; 1.0707x over previous
#include <cuda_runtime.h>

#define IN_DIM  1024
#define OUT_DIM 512
#define B_DIM   128
#define OT      16                  // output tile per block
#define ICH     32                  // input chunk per block
#define NSPLIT  (IN_DIM / ICH)      // 32 partials per (b,o)

// Partial sums: [split][b][o]  (32 * 128 * 512 * 4B = 8 MB)
__device__ float g_part[NSPLIT * B_DIM * OUT_DIM];

__device__ __forceinline__ float tanh_approx(float x) {
    float y;
    asm("tanh.approx.f32 %0, %1;" : "=f"(y) : "f"(x));
    return y;
}
__device__ __forceinline__ float rcp_approx(float x) {
    float y;
    asm("rcp.approx.f32 %0, %1;" : "=f"(y) : "f"(x));
    return y;
}

__device__ __forceinline__ float weff_one(float4 t, float w) {
    float a = __expf(t.x), b = __expf(t.y), c = __expf(t.z), d = __expf(t.w);
    float inv = rcp_approx(a + b + c + d);
    return (b * w + c * tanh_approx(w) + d * __sinf(w)) * inv;
}

// Fused kernel: each block owns (o-tile 16, i-chunk 32, ALL 128 batches).
// 1) computes its 16x32 W_eff tile (each element exactly once, chip-wide)
// 2) stages the 128x32 x tile
// 3) partial[split][b][o] = sum_{i in chunk} tanh(x[b,i] * W_eff[o,i])
__global__ __launch_bounds__(256, 7)
void fbn_fused_kernel(const float* __restrict__ x,
                      const float* __restrict__ W,
                      const float* __restrict__ theta) {
    __shared__ float ws_t[ICH][OT];          // W_eff transposed [i][o], 2 KB
    __shared__ float xs[B_DIM][ICH];         // x tile [b][i], 16 KB

    const int tid = threadIdx.x;
    const int o0 = blockIdx.x * OT;
    const int c0 = blockIdx.y * ICH;

    // ---- W_eff tile: 512 elements, 2 per thread (m = tid, tid+256) ----
    {
        const float4* t4 = reinterpret_cast<const float4*>(theta);
        int m0 = tid, m1 = tid + 256;
        int ol0 = m0 >> 5, il0 = m0 & 31;
        int ol1 = m1 >> 5, il1 = m1 & 31;
        int g0 = (o0 + ol0) * IN_DIM + c0 + il0;
        int g1 = (o0 + ol1) * IN_DIM + c0 + il1;
        float4 ta = t4[g0];
        float4 tb = t4[g1];
        float wa = W[g0];
        float wb = W[g1];
        ws_t[il0][ol0] = weff_one(ta, wa);
        ws_t[il1][ol1] = weff_one(tb, wb);
    }

    // ---- x tile: 128 rows x 8 float4 = 1024 float4, 4 per thread ----
    {
        const float4* xg = reinterpret_cast<const float4*>(x);
        #pragma unroll
        for (int k = 0; k < 4; k++) {
            int f = tid + k * 256;
            int row = f >> 3, col = f & 7;
            float4 v = xg[row * (IN_DIM / 4) + (c0 >> 2) + col];
            *reinterpret_cast<float4*>(&xs[row][col * 4]) = v;
        }
    }
    __syncthreads();

    // ---- compute: thread = (o = tx, batches ty*8 .. ty*8+7) ----
    const int tx = tid & 15;
    const int ty = tid >> 4;
    const float* xrow = &xs[ty * 8][0];

    float acc0 = 0.f, acc1 = 0.f, acc2 = 0.f, acc3 = 0.f;
    float acc4 = 0.f, acc5 = 0.f, acc6 = 0.f, acc7 = 0.f;

    #pragma unroll 8
    for (int i = 0; i < ICH; i++) {
        float w = ws_t[i][tx];
        acc0 += tanh_approx(xrow[0 * ICH + i] * w);
        acc1 += tanh_approx(xrow[1 * ICH + i] * w);
        acc2 += tanh_approx(xrow[2 * ICH + i] * w);
        acc3 += tanh_approx(xrow[3 * ICH + i] * w);
        acc4 += tanh_approx(xrow[4 * ICH + i] * w);
        acc5 += tanh_approx(xrow[5 * ICH + i] * w);
        acc6 += tanh_approx(xrow[6 * ICH + i] * w);
        acc7 += tanh_approx(xrow[7 * ICH + i] * w);
    }

    float* dst = g_part + (blockIdx.y * B_DIM + ty * 8) * OUT_DIM + o0 + tx;
    dst[0 * OUT_DIM] = acc0;
    dst[1 * OUT_DIM] = acc1;
    dst[2 * OUT_DIM] = acc2;
    dst[3 * OUT_DIM] = acc3;
    dst[4 * OUT_DIM] = acc4;
    dst[5 * OUT_DIM] = acc5;
    dst[6 * OUT_DIM] = acc6;
    dst[7 * OUT_DIM] = acc7;
}

// Reduce: out[b][o] = bias[o] + sum_s partial[s][b][o]   (partials L2-resident)
__global__ __launch_bounds__(256)
void reduce_kernel(const float* __restrict__ bias,
                   float* __restrict__ out) {
    int idx = blockIdx.x * blockDim.x + threadIdx.x;   // 0..65535
    float s = bias[idx & (OUT_DIM - 1)];
    #pragma unroll
    for (int p = 0; p < NSPLIT; p++)
        s += g_part[p * B_DIM * OUT_DIM + idx];
    out[idx] = s;
}

extern "C" void kernel_launch(void* const* d_in, const int* in_sizes, int n_in,
                              void* d_out, int out_size) {
    const float* x     = (const float*)d_in[0];   // (128, 1024)
    const float* W     = (const float*)d_in[1];   // (512, 1024)
    const float* bias  = (const float*)d_in[2];   // (512,)
    const float* theta = (const float*)d_in[3];   // (512, 1024, 4)
    float* out = (float*)d_out;                   // (128, 512)

    (void)in_sizes; (void)n_in; (void)out_size;

    dim3 grid(OUT_DIM / OT, IN_DIM / ICH);   // (32, 32) = 1024 blocks, 1 wave @ 7/SM
    fbn_fused_kernel<<<grid, 256>>>(x, W, theta);

    reduce_kernel<<<(B_DIM * OUT_DIM) / 256, 256>>>(bias, out);
}